// round 12
// baseline (speedup 1.0000x reference)
#include <cuda_runtime.h>
#include <cuda_bf16.h>
#include <cstdint>

// Problem dims
#define BBATCH 8
#define CTX    4096
#define QSTN   512
#define EDIM   300
#define HDIM   128

// Scratch (device globals: no allocation allowed in kernel_launch)
__device__ float g_ctx_logits[(size_t)BBATCH * CTX  * HDIM];   // 16 MB
__device__ float g_qst_logits[(size_t)BBATCH * QSTN * HDIM];   // 2 MB

// ---- tf32 mma helpers -----------------------------------------------------
__device__ __forceinline__ unsigned cvt_tf32(float f) {
    unsigned u; asm("cvt.rna.tf32.f32 %0, %1;" : "=r"(u) : "f"(f)); return u;
}
__device__ __forceinline__ float cvtf_tf32(float f) {
    return __uint_as_float(cvt_tf32(f));
}
// D(16x8,f32) += A(16x8,tf32,row) * B(8x8,tf32,col)
__device__ __forceinline__ void mma8(float& d0, float& d1, float& d2, float& d3,
                                     unsigned a0, unsigned a1, unsigned a2, unsigned a3,
                                     unsigned b0, unsigned b1) {
    asm volatile("mma.sync.aligned.m16n8k8.row.col.f32.tf32.tf32.f32 "
                 "{%0,%1,%2,%3}, {%4,%5,%6,%7}, {%8,%9}, {%0,%1,%2,%3};"
                 : "+f"(d0), "+f"(d1), "+f"(d2), "+f"(d3)
                 : "r"(a0), "r"(a1), "r"(a2), "r"(a3), "r"(b0), "r"(b1));
}

// ---------------------------------------------------------------------------
// Kernel 1: logits = ReLU(x @ W^T + b), 2xTF32 compensated (unchanged, ~42us)
// ---------------------------------------------------------------------------
#define KSP 20   // smem row stride: 20 mod 32 -> conflict-free frag loads

__global__ __launch_bounds__(256) void logits_mma(const float* __restrict__ ctx,
                                                  const float* __restrict__ qst,
                                                  const float* __restrict__ W,
                                                  const float* __restrict__ bias,
                                                  float* __restrict__ ctxL,
                                                  float* __restrict__ qstL) {
    __shared__ float xh[128 * KSP], xl[128 * KSP];
    __shared__ float wh[128 * KSP];
    __shared__ float bs[HDIM];

    const int tid  = threadIdx.x;
    const int warp = tid >> 5, lane = tid & 31;
    const int rl   = lane >> 2, cl = lane & 3;

    const bool is_ctx = (blockIdx.x < 256);
    const int  row0   = (is_ctx ? blockIdx.x : (blockIdx.x - 256)) * 128;
    const float* x    = is_ctx ? ctx  : qst;
    float*       out  = is_ctx ? ctxL : qstL;

    if (tid < HDIM) bs[tid] = bias[tid];

    float d[16][4];
#pragma unroll
    for (int t = 0; t < 16; t++)
#pragma unroll
        for (int i = 0; i < 4; i++) d[t][i] = 0.0f;

    for (int s = 0; s < 19; s++) {              // 19*16 = 304 >= 300
        const int k0 = s * 16;
        __syncthreads();
#pragma unroll
        for (int i = 0; i < 4; i++) {
            int f = tid + 256 * i;
            if (f < 512) {
                const int r  = f >> 2;
                const int c4 = (f & 3) << 2;
                const int ge = k0 + c4;
                float4 v = make_float4(0.f, 0.f, 0.f, 0.f);
                if (ge + 3 < EDIM) v = *(const float4*)(x + (size_t)(row0 + r) * EDIM + ge);
                float4 h4, l4;
                h4.x = cvtf_tf32(v.x); l4.x = cvtf_tf32(v.x - h4.x);
                h4.y = cvtf_tf32(v.y); l4.y = cvtf_tf32(v.y - h4.y);
                h4.z = cvtf_tf32(v.z); l4.z = cvtf_tf32(v.z - h4.z);
                h4.w = cvtf_tf32(v.w); l4.w = cvtf_tf32(v.w - h4.w);
                *(float4*)(xh + r * KSP + c4) = h4;
                *(float4*)(xl + r * KSP + c4) = l4;
            } else {
                f -= 512;
                const int r  = f >> 2;
                const int c4 = (f & 3) << 2;
                const int ge = k0 + c4;
                float4 v = make_float4(0.f, 0.f, 0.f, 0.f);
                if (ge + 3 < EDIM) v = *(const float4*)(W + (size_t)r * EDIM + ge);
                float4 h4;
                h4.x = cvtf_tf32(v.x);
                h4.y = cvtf_tf32(v.y);
                h4.z = cvtf_tf32(v.z);
                h4.w = cvtf_tf32(v.w);
                *(float4*)(wh + r * KSP + c4) = h4;
            }
        }
        __syncthreads();

#pragma unroll
        for (int kk = 0; kk < 16; kk += 8) {
            const int ab = (warp * 16 + rl) * KSP + kk + cl;
            unsigned ah0 = __float_as_uint(xh[ab]);
            unsigned ah1 = __float_as_uint(xh[ab + 8 * KSP]);
            unsigned ah2 = __float_as_uint(xh[ab + 4]);
            unsigned ah3 = __float_as_uint(xh[ab + 8 * KSP + 4]);
            unsigned al0 = __float_as_uint(xl[ab]);
            unsigned al1 = __float_as_uint(xl[ab + 8 * KSP]);
            unsigned al2 = __float_as_uint(xl[ab + 4]);
            unsigned al3 = __float_as_uint(xl[ab + 8 * KSP + 4]);
#pragma unroll
            for (int t = 0; t < 16; t++) {
                const int bi = (t * 8 + rl) * KSP + kk + cl;
                unsigned bh0 = __float_as_uint(wh[bi]), bh1 = __float_as_uint(wh[bi + 4]);
                mma8(d[t][0], d[t][1], d[t][2], d[t][3], ah0, ah1, ah2, ah3, bh0, bh1);
                mma8(d[t][0], d[t][1], d[t][2], d[t][3], al0, al1, al2, al3, bh0, bh1);
            }
        }
    }

    const int rlo = row0 + warp * 16 + rl;
    const int rhi = rlo + 8;
#pragma unroll
    for (int t = 0; t < 16; t++) {
        const int c0 = t * 8 + 2 * cl;
        const float b0 = bs[c0], b1 = bs[c0 + 1];
        float2 v0, v1;
        v0.x = cvtf_tf32(fmaxf(d[t][0] + b0, 0.0f));
        v0.y = cvtf_tf32(fmaxf(d[t][1] + b1, 0.0f));
        v1.x = cvtf_tf32(fmaxf(d[t][2] + b0, 0.0f));
        v1.y = cvtf_tf32(fmaxf(d[t][3] + b1, 0.0f));
        *(float2*)(out + (size_t)rlo * HDIM + c0) = v0;
        *(float2*)(out + (size_t)rhi * HDIM + c0) = v1;
    }
}

// ---------------------------------------------------------------------------
// Kernel 2: fused flash attention, tf32 mma, M_t=2 warp tiles.
// Block: 128 ctx rows, 256 threads (8 warps = 4 pairs). Pair owns 32 rows
// (two m16 tiles). Phase1 splits the 64-q chunk across the pair (32 q each);
// phase2 splits h (64 each). B fragments loaded once per t, reused by both
// M-tiles -> LDS/mma drops 3.0->2.0 (p1) and 2.5->1.5 (p2).
// 1 CTA/SM (141 KB smem), latency hidden by 64-chain ILP.
// ---------------------------------------------------------------------------
#define CSP 132   // mod 32 = 4 -> A frags conflict-free
#define QSP 136   // + (q&4) row shift -> conflict-free both phases
#define PSP 68    // mod 32 = 4 -> phase2 A conflict-free
// floats: cs 128*132=16896, qs 64*136=8704, ps 4*32*68=8704, red 512 -> 34816
#define ATTN_SMEM (34816 * 4 + QSTN * 4)   // 141312 B -> 1 CTA/SM

__global__ __launch_bounds__(256, 1) void attn_mma(const float* __restrict__ ctxL,
                                                   const float* __restrict__ qstL,
                                                   const int*   __restrict__ mask,
                                                   float* __restrict__ out) {
    extern __shared__ float sm[];
    float* cs   = sm;                     // 128 x 132
    float* qs   = cs + 128 * CSP;         // 64 x 136 (Q and V view, row-shifted)
    float* ps   = qs + 64 * QSP;          // [4 pairs][32 rows][68]
    float* redm = ps + 4 * 32 * PSP;      // [4][2][32] partial row max
    float* reds = redm + 256;             // [4][2][32] partial row sum
    int*   ms   = (int*)(reds + 256);     // 512

    const int tid  = threadIdx.x;
    const int warp = tid >> 5, lane = tid & 31;
    const int rl   = lane >> 2, cl = lane & 3;
    const int pair = warp >> 1, half = warp & 1;
    const int bb   = blockIdx.x >> 5;     // CTX/128 = 32 blocks per batch
    const int ct   = blockIdx.x & 31;
    const int row0 = ct * 128;
    const int r0   = pair * 32;           // pair's rows within block
    float* pr = ps + pair * 32 * PSP;

    const float* cbase = ctxL + ((size_t)bb * CTX + row0) * HDIM;
    const float* qbase = qstL + (size_t)bb * QSTN * HDIM;

    for (int f = tid; f < 4096; f += 256) {
        const int r = f >> 5, h4 = (f & 31) << 2;
        *(float4*)(cs + r * CSP + h4) = *(const float4*)(cbase + (size_t)r * HDIM + h4);
    }
    for (int i = tid; i < QSTN; i += 256) ms[i] = mask[bb * QSTN + i];

    const float NEG_INF = __int_as_float(0xff800000);
    float o[2][8][4];
#pragma unroll
    for (int m = 0; m < 2; m++)
#pragma unroll
        for (int t = 0; t < 8; t++)
#pragma unroll
            for (int i = 0; i < 4; i++) o[m][t][i] = 0.0f;
    float m_i[2][2], l_i[2][2];
#pragma unroll
    for (int m = 0; m < 2; m++) {
        m_i[m][0] = NEG_INF; m_i[m][1] = NEG_INF;
        l_i[m][0] = 0.0f;    l_i[m][1] = 0.0f;
    }

    for (int qc = 0; qc < QSTN / 64; qc++) {
        __syncthreads();               // previous chunk fully consumed (qs, ps, red)
        for (int f = tid; f < 2048; f += 256) {
            const int q = f >> 5, h4 = (f & 31) << 2;
            *(float4*)(qs + q * QSP + h4 + (q & 4)) =
                *(const float4*)(qbase + (size_t)qc * 64 * HDIM + (size_t)q * HDIM + h4);
        }
        __syncthreads();

        // ---- phase 1: S[32 x 32] = C @ Q^T (pair rows, this warp's q half)
        float s[2][4][4];
#pragma unroll
        for (int m = 0; m < 2; m++)
#pragma unroll
            for (int t = 0; t < 4; t++)
#pragma unroll
                for (int i = 0; i < 4; i++) s[m][t][i] = 0.0f;

#pragma unroll
        for (int k0 = 0; k0 < HDIM; k0 += 8) {
            unsigned a[2][4];
#pragma unroll
            for (int m = 0; m < 2; m++) {
                const int ab = (r0 + m * 16 + rl) * CSP + k0 + cl;
                a[m][0] = __float_as_uint(cs[ab]);
                a[m][1] = __float_as_uint(cs[ab + 8 * CSP]);
                a[m][2] = __float_as_uint(cs[ab + 4]);
                a[m][3] = __float_as_uint(cs[ab + 8 * CSP + 4]);
            }
#pragma unroll
            for (int t = 0; t < 4; t++) {
                // q = half*32 + t*8 + rl  ->  (q & 4) == (rl & 4)
                const int bi = (half * 32 + t * 8 + rl) * QSP + k0 + cl + (rl & 4);
                unsigned b0 = __float_as_uint(qs[bi]);
                unsigned b1 = __float_as_uint(qs[bi + 4]);
#pragma unroll
                for (int m = 0; m < 2; m++)
                    mma8(s[m][t][0], s[m][t][1], s[m][t][2], s[m][t][3],
                         a[m][0], a[m][1], a[m][2], a[m][3], b0, b1);
            }
        }

        // ---- masked partial row max over this half -----------------------
        const int qb = qc * 64 + half * 32;
        float mx[2][2];
#pragma unroll
        for (int m = 0; m < 2; m++) { mx[m][0] = NEG_INF; mx[m][1] = NEG_INF; }
#pragma unroll
        for (int t = 0; t < 4; t++) {
            const int c0 = t * 8 + 2 * cl;
            const int m0 = ms[qb + c0], m1 = ms[qb + c0 + 1];
#pragma unroll
            for (int m = 0; m < 2; m++) {
                if (m0) { mx[m][0] = fmaxf(mx[m][0], s[m][t][0]); mx[m][1] = fmaxf(mx[m][1], s[m][t][2]); }
                if (m1) { mx[m][0] = fmaxf(mx[m][0], s[m][t][1]); mx[m][1] = fmaxf(mx[m][1], s[m][t][3]); }
            }
        }
#pragma unroll
        for (int off = 1; off <= 2; off <<= 1)
#pragma unroll
            for (int m = 0; m < 2; m++) {
                mx[m][0] = fmaxf(mx[m][0], __shfl_xor_sync(0xffffffffu, mx[m][0], off));
                mx[m][1] = fmaxf(mx[m][1], __shfl_xor_sync(0xffffffffu, mx[m][1], off));
            }
        if (cl == 0) {
#pragma unroll
            for (int m = 0; m < 2; m++) {
                redm[(pair * 2 + half) * 32 + m * 16 + rl]     = mx[m][0];
                redm[(pair * 2 + half) * 32 + m * 16 + rl + 8] = mx[m][1];
            }
        }
        asm volatile("bar.sync %0, 64;" :: "r"(pair + 1) : "memory");
        float sc[2][2], mn[2][2];
#pragma unroll
        for (int m = 0; m < 2; m++) {
            mx[m][0] = fmaxf(mx[m][0], redm[(pair * 2 + (1 - half)) * 32 + m * 16 + rl]);
            mx[m][1] = fmaxf(mx[m][1], redm[(pair * 2 + (1 - half)) * 32 + m * 16 + rl + 8]);
            mn[m][0] = fmaxf(m_i[m][0], mx[m][0]);
            mn[m][1] = fmaxf(m_i[m][1], mx[m][1]);
            sc[m][0] = (m_i[m][0] == NEG_INF) ? 0.0f : __expf(m_i[m][0] - mn[m][0]);
            sc[m][1] = (m_i[m][1] == NEG_INF) ? 0.0f : __expf(m_i[m][1] - mn[m][1]);
        }

        // ---- exp, P -> smem (this half's cols), partial sums -------------
        float sum[2][2];
#pragma unroll
        for (int m = 0; m < 2; m++) { sum[m][0] = 0.0f; sum[m][1] = 0.0f; }
#pragma unroll
        for (int t = 0; t < 4; t++) {
            const int c0 = t * 8 + 2 * cl;
            const int m0 = ms[qb + c0], m1 = ms[qb + c0 + 1];
            const int col = half * 32 + c0;
#pragma unroll
            for (int m = 0; m < 2; m++) {
                float p0 = m0 ? cvtf_tf32(__expf(s[m][t][0] - mn[m][0])) : 0.0f;
                float p1 = m1 ? cvtf_tf32(__expf(s[m][t][1] - mn[m][0])) : 0.0f;
                float p2 = m0 ? cvtf_tf32(__expf(s[m][t][2] - mn[m][1])) : 0.0f;
                float p3 = m1 ? cvtf_tf32(__expf(s[m][t][3] - mn[m][1])) : 0.0f;
                sum[m][0] += p0 + p1;
                sum[m][1] += p2 + p3;
                *(float2*)(pr + (m * 16 + rl) * PSP + col)     = make_float2(p0, p1);
                *(float2*)(pr + (m * 16 + 8 + rl) * PSP + col) = make_float2(p2, p3);
            }
        }
#pragma unroll
        for (int off = 1; off <= 2; off <<= 1)
#pragma unroll
            for (int m = 0; m < 2; m++) {
                sum[m][0] += __shfl_xor_sync(0xffffffffu, sum[m][0], off);
                sum[m][1] += __shfl_xor_sync(0xffffffffu, sum[m][1], off);
            }
        if (cl == 0) {
#pragma unroll
            for (int m = 0; m < 2; m++) {
                reds[(pair * 2 + half) * 32 + m * 16 + rl]     = sum[m][0];
                reds[(pair * 2 + half) * 32 + m * 16 + rl + 8] = sum[m][1];
            }
        }
        asm volatile("bar.sync %0, 64;" :: "r"(pair + 1) : "memory");  // also orders ps
#pragma unroll
        for (int m = 0; m < 2; m++) {
            sum[m][0] += reds[(pair * 2 + (1 - half)) * 32 + m * 16 + rl];
            sum[m][1] += reds[(pair * 2 + (1 - half)) * 32 + m * 16 + rl + 8];
            l_i[m][0] = l_i[m][0] * sc[m][0] + sum[m][0];
            l_i[m][1] = l_i[m][1] * sc[m][1] + sum[m][1];
            m_i[m][0] = mn[m][0]; m_i[m][1] = mn[m][1];
#pragma unroll
            for (int t = 0; t < 8; t++) {
                o[m][t][0] *= sc[m][0]; o[m][t][1] *= sc[m][0];
                o[m][t][2] *= sc[m][1]; o[m][t][3] *= sc[m][1];
            }
        }

        // ---- phase 2: O[32 x 64] += P @ V (this warp's h half) -----------
#pragma unroll
        for (int k0 = 0; k0 < 64; k0 += 8) {
            unsigned a[2][4];
#pragma unroll
            for (int m = 0; m < 2; m++) {
                const int ab = (m * 16 + rl) * PSP + k0 + cl;
                a[m][0] = __float_as_uint(pr[ab]);
                a[m][1] = __float_as_uint(pr[ab + 8 * PSP]);
                a[m][2] = __float_as_uint(pr[ab + 4]);
                a[m][3] = __float_as_uint(pr[ab + 8 * PSP + 4]);
            }
#pragma unroll
            for (int t = 0; t < 8; t++) {
                const int hcol = half * 64 + t * 8 + rl;
                // b0: row q=k0+cl   -> shift (q&4)==0; b1: row q=k0+cl+4 -> shift +4
                const int bi0 = (k0 + cl) * QSP + hcol;
                const int bi1 = (k0 + cl + 4) * QSP + hcol + 4;
                unsigned b0 = __float_as_uint(qs[bi0]);
                unsigned b1 = __float_as_uint(qs[bi1]);
#pragma unroll
                for (int m = 0; m < 2; m++)
                    mma8(o[m][t][0], o[m][t][1], o[m][t][2], o[m][t][3],
                         a[m][0], a[m][1], a[m][2], a[m][3], b0, b1);
            }
        }
    }

    // ---- epilogue: normalize + store -------------------------------------
    float* ob = out + ((size_t)bb * CTX + row0) * HDIM;
#pragma unroll
    for (int m = 0; m < 2; m++) {
        const float inv_lo = 1.0f / l_i[m][0];
        const float inv_hi = 1.0f / l_i[m][1];
        const int rlo = r0 + m * 16 + rl, rhi = rlo + 8;
#pragma unroll
        for (int t = 0; t < 8; t++) {
            const int c0 = half * 64 + t * 8 + 2 * cl;
            *(float2*)(ob + (size_t)rlo * HDIM + c0) =
                make_float2(o[m][t][0] * inv_lo, o[m][t][1] * inv_lo);
            *(float2*)(ob + (size_t)rhi * HDIM + c0) =
                make_float2(o[m][t][2] * inv_hi, o[m][t][3] * inv_hi);
        }
    }
}

// ---------------------------------------------------------------------------
extern "C" void kernel_launch(void* const* d_in, const int* in_sizes, int n_in,
                              void* d_out, int out_size) {
    const float* ctx  = (const float*)d_in[0];   // [8,4096,300]
    const float* qst  = (const float*)d_in[1];   // [8,512,300]
    const int*   mask = (const int*)d_in[2];     // [8,512]
    const float* W    = (const float*)d_in[3];   // [128,300]
    const float* bias = (const float*)d_in[4];   // [128]
    float*       out  = (float*)d_out;           // [8,4096,128]

    cudaFuncSetAttribute(attn_mma, cudaFuncAttributeMaxDynamicSharedMemorySize, ATTN_SMEM);

    void* p_ctxL = nullptr; void* p_qstL = nullptr;
    cudaGetSymbolAddress(&p_ctxL, g_ctx_logits);
    cudaGetSymbolAddress(&p_qstL, g_qst_logits);
    float* ctxL = (float*)p_ctxL;
    float* qstL = (float*)p_qstL;

    // fused logits: blocks [0,256) ctx rows, [256,288) qst rows
    logits_mma<<<288, 256>>>(ctx, qst, W, bias, ctxL, qstL);

    // fused scores -> online softmax -> AV (128 ctx rows, 8 warps per block)
    attn_mma<<<BBATCH * (CTX / 128), 256, ATTN_SMEM>>>(ctxL, qstL, mask, out);
}